// round 14
// baseline (speedup 1.0000x reference)
#include <cuda_runtime.h>
#include <cuda_bf16.h>
#include <math.h>
#include <stdint.h>

#define BB 16
#define NN 4096
#define CC 256
#define KK 8
#define EPSF 1e-6f
#define RATIOF 0.1f
#define NTOK (BB*NN)          // 65536
#define GATE_BLOCKS (NTOK/16) // 4096
#define NITEMS (BB*KK*2)      // 256 expert items: (k, b, halfM) k-major
#define ROWB 528

// ---------------- scratch globals ----------------
__device__ unsigned short g_route_e[NTOK];
__device__ float2         g_route_w[NTOK];
__device__ float          g_conf[GATE_BLOCKS];
__device__ float          g_hacc[BB*KK*CC];
__device__ float          g_mass[BB*KK];
__device__ unsigned short g_list[BB*KK][NN];
__device__ float          g_wt[BB*KK][NN];
__device__ int            g_cnt[BB*KK];
__device__ int            g_item;
__device__ __nv_bfloat16  g_tokbf[(size_t)NTOK*CC];       // bf16 tokens (gate writes)
__device__ char           g_w1pad[(size_t)KK*256*ROWB];   // W1 bf16, padded rows

// ---------------- helpers ----------------
__device__ __forceinline__ uint32_t smem_u32(const void* p) {
    uint32_t a;
    asm("{ .reg .u64 t; cvta.to.shared.u64 t, %1; cvt.u32.u64 %0, t; }" : "=r"(a) : "l"(p));
    return a;
}
__device__ __forceinline__ uint32_t pack_bf2(float a, float b) {
    uint32_t r;
    asm("cvt.rn.bf16x2.f32 %0, %1, %2;" : "=r"(r) : "f"(b), "f"(a));
    return r;
}
__device__ __forceinline__ void mma16816(float* c, const uint32_t* a, const uint32_t* b) {
    asm volatile("mma.sync.aligned.m16n8k16.row.col.f32.bf16.bf16.f32 "
        "{%0,%1,%2,%3}, {%4,%5,%6,%7}, {%8,%9}, {%0,%1,%2,%3};"
        : "+f"(c[0]), "+f"(c[1]), "+f"(c[2]), "+f"(c[3])
        : "r"(a[0]), "r"(a[1]), "r"(a[2]), "r"(a[3]), "r"(b[0]), "r"(b[1]));
}
#define LDSM4(r, addr) \
    asm volatile("ldmatrix.sync.aligned.m8n8.x4.shared.b16 {%0,%1,%2,%3}, [%4];" \
        : "=r"((r)[0]), "=r"((r)[1]), "=r"((r)[2]), "=r"((r)[3]) : "r"(addr))
#define CP_ASYNC16(dst, src) \
    asm volatile("cp.async.cg.shared.global [%0], [%1], 16;" :: "r"(dst), "l"(src))
#define CP_COMMIT() asm volatile("cp.async.commit_group;" ::: "memory")
#define CP_WAIT0()  asm volatile("cp.async.wait_group 0;" ::: "memory")

// ------- gate (blocks 0..4095): geno + logits/top-2/softmax + bf16 copy
// ------- w1pad (blocks 4096..4223): W1 -> padded bf16 global (independent work)
__global__ void gate_kernel(const float* __restrict__ tokens,
                            const float* __restrict__ Wg,
                            const float* __restrict__ bg,
                            const float* __restrict__ geno_vec,
                            const float* __restrict__ Wgg,
                            const float* __restrict__ bgg,
                            const float* __restrict__ W1) {
    int tid = threadIdx.x;
    if (blockIdx.x >= GATE_BLOCKS) {
        int gid = (blockIdx.x - GATE_BLOCKS) * 256 + tid;
        int row = gid >> 4, seg = gid & 15;
        const float4* src = (const float4*)(W1 + (size_t)row * CC) + seg * 4;
        char* dst = g_w1pad + (size_t)row * ROWB + seg * 32;
#pragma unroll
        for (int j = 0; j < 4; j++) {
            float4 v = src[j];
            *(uint2*)(dst + j * 8) = make_uint2(pack_bf2(v.x, v.y), pack_bf2(v.z, v.w));
        }
        return;
    }

    __shared__ float4 sWg[KK * 64];
    __shared__ float  sconf[16];
    __shared__ float  sbg[8], sgeno[8];
    int warp = tid >> 5, lane = tid & 31;
    int b = (blockIdx.x * 16) >> 12;

    for (int i = tid; i < KK * 64; i += 256) sWg[i] = ((const float4*)Wg)[i];
    // per-block geno term: warp w computes k=w
    {
        const float4* g4 = (const float4*)(geno_vec + b * CC);
        const float4* w4 = (const float4*)(Wgg + warp * CC);
        float4 ga = g4[lane * 2], gb = g4[lane * 2 + 1];
        float4 wa = w4[lane * 2], wb = w4[lane * 2 + 1];
        float d = ga.x * wa.x + ga.y * wa.y + ga.z * wa.z + ga.w * wa.w
                + gb.x * wb.x + gb.y * wb.y + gb.z * wb.z + gb.w * wb.w;
#pragma unroll
        for (int off = 16; off; off >>= 1) d += __shfl_xor_sync(0xffffffffu, d, off);
        if (lane == 0) sgeno[warp] = RATIOF * (d + bgg[warp]);
    }
    if (tid < 8) sbg[tid] = bg[tid];
    __syncthreads();

    int t0 = blockIdx.x * 16 + warp * 2;

    float acc[2][KK];
#pragma unroll
    for (int u = 0; u < 2; u++)
#pragma unroll
        for (int k = 0; k < KK; k++) acc[u][k] = 0.f;

    uint2* bf0 = (uint2*)(g_tokbf + (size_t)t0 * CC);
    uint2* bf1 = (uint2*)(g_tokbf + (size_t)(t0 + 1) * CC);
#pragma unroll
    for (int i = 0; i < 2; i++) {
        float4 tv0 = ((const float4*)(tokens + (size_t)t0 * CC))[i * 32 + lane];
        float4 tv1 = ((const float4*)(tokens + (size_t)(t0 + 1) * CC))[i * 32 + lane];
        bf0[i * 32 + lane] = make_uint2(pack_bf2(tv0.x, tv0.y), pack_bf2(tv0.z, tv0.w));
        bf1[i * 32 + lane] = make_uint2(pack_bf2(tv1.x, tv1.y), pack_bf2(tv1.z, tv1.w));
#pragma unroll
        for (int k = 0; k < KK; k++) {
            float4 w = sWg[k * 64 + i * 32 + lane];
            acc[0][k] += tv0.x * w.x + tv0.y * w.y + tv0.z * w.z + tv0.w * w.w;
            acc[1][k] += tv1.x * w.x + tv1.y * w.y + tv1.z * w.z + tv1.w * w.w;
        }
    }

    // multi-field butterfly reduce: 16 (token,k) fields over 32 lanes
    const unsigned FM = 0xffffffffu;
    float tt[8];
#pragma unroll
    for (int kk = 0; kk < 8; kk++) {
        float send = (lane & 16) ? acc[0][kk] : acc[1][kk];
        float keep = (lane & 16) ? acc[1][kk] : acc[0][kk];
        tt[kk] = keep + __shfl_xor_sync(FM, send, 16);
    }
    float uu[4];
#pragma unroll
    for (int j = 0; j < 4; j++) {
        float send = (lane & 8) ? tt[j] : tt[j + 4];
        float keep = (lane & 8) ? tt[j + 4] : tt[j];
        uu[j] = keep + __shfl_xor_sync(FM, send, 8);
    }
    float vv[2];
#pragma unroll
    for (int j = 0; j < 2; j++) {
        float send = (lane & 4) ? uu[j] : uu[j + 2];
        float keep = (lane & 4) ? uu[j + 2] : uu[j];
        vv[j] = keep + __shfl_xor_sync(FM, send, 4);
    }
    float ww;
    {
        float send = (lane & 2) ? vv[0] : vv[1];
        float keep = (lane & 2) ? vv[1] : vv[0];
        ww = keep + __shfl_xor_sync(FM, send, 2);
    }
    ww += __shfl_xor_sync(FM, ww, 1);

    float gk[8];
#pragma unroll
    for (int k = 0; k < 8; k++)
        gk[k] = __shfl_sync(FM, ww, (lane & 16) | (k << 1));

    if ((lane & 15) == 0) {
        int u = lane >> 4;
        int t = t0 + u;
        float lg[KK];
#pragma unroll
        for (int k = 0; k < KK; k++) lg[k] = gk[k] + sbg[k] + sgeno[k];
        int i0 = 0; float v0 = lg[0];
#pragma unroll
        for (int k = 1; k < KK; k++) if (lg[k] > v0) { v0 = lg[k]; i0 = k; }
        float v1 = -1e30f; int i1 = 0;
#pragma unroll
        for (int k = 0; k < KK; k++)
            if (k != i0 && lg[k] > v1) { v1 = lg[k]; i1 = k; }
        float e  = expf(v1 - v0);
        float w0 = 1.f / (1.f + e);
        float w1 = e / (1.f + e);
        w0 = fmaxf(w0, EPSF); w1 = fmaxf(w1, EPSF);
        float s = w0 + w1; w0 /= s; w1 /= s;
        g_route_e[t] = (unsigned short)(i0 | (i1 << 8));
        g_route_w[t] = make_float2(w0, w1);
        sconf[warp * 2 + u] = v0 - v1;
    }
    __syncthreads();
    if (tid == 0) {
        float cs = 0.f;
#pragma unroll
        for (int w = 0; w < 16; w++) cs += sconf[w];
        g_conf[blockIdx.x] = cs;
    }
}

// ------- compaction (blocks 0-127) + hacc zero/counter (block 128) -------
__global__ void compact_kernel() {
    int tid = threadIdx.x;
    if (blockIdx.x == 128) {
        float4* h4 = (float4*)g_hacc;
        for (int i = tid; i < BB * KK * CC / 4; i += 256)
            h4[i] = make_float4(0.f, 0.f, 0.f, 0.f);
        if (tid == 0) g_item = 0;
        return;
    }
    __shared__ int   scnt[8];
    __shared__ float smass[8];
    __shared__ int   soff[8];
    int bk = blockIdx.x;
    int b = bk >> 3, k = bk & 7;
    int warp = tid >> 5, lane = tid & 31;

    int cnt = 0; float mass = 0.f;
    int base0 = warp * 512;
    for (int i = 0; i < 16; i++) {
        int n = base0 + i * 32 + lane;
        unsigned short e = g_route_e[b * NN + n];
        float2 wv = g_route_w[b * NN + n];
        bool m0 = (e & 0xff) == k;
        bool m1 = (e >> 8)   == k;
        bool hit = m0 || m1;
        unsigned bal = __ballot_sync(0xffffffffu, hit);
        cnt += __popc(bal);
        if (hit) mass += m0 ? wv.x : wv.y;
    }
#pragma unroll
    for (int off = 16; off; off >>= 1) mass += __shfl_xor_sync(0xffffffffu, mass, off);
    if (lane == 0) { scnt[warp] = cnt; smass[warp] = mass; }
    __syncthreads();
    if (tid == 0) {
        int run = 0; float msum = 0.f;
#pragma unroll
        for (int w = 0; w < 8; w++) { soff[w] = run; run += scnt[w]; msum += smass[w]; }
        g_cnt[bk] = run;
        g_mass[bk] = msum;
    }
    __syncthreads();

    int pos = soff[warp];
    for (int i = 0; i < 16; i++) {
        int n = base0 + i * 32 + lane;
        unsigned short e = g_route_e[b * NN + n];
        float2 wv = g_route_w[b * NN + n];
        bool m0 = (e & 0xff) == k;
        bool m1 = (e >> 8)   == k;
        bool hit = m0 || m1;
        unsigned bal = __ballot_sync(0xffffffffu, hit);
        if (hit) {
            int p = pos + __popc(bal & ((1u << lane) - 1u));
            g_list[bk][p] = (unsigned short)n;
            g_wt[bk][p]   = m0 ? wv.x : wv.y;
        }
        pos += __popc(bal);
    }
}

// ================= expert: 1 block/SM, M=64 x N=256, 8 warps of 64x32, A dbl-buf =================
// Items decoded k-major so consecutive items on an SM share k -> skip B re-stage.
#define OFF_B    0                                  // 256 x 528 = 135168
#define OFF_A0   (256 * ROWB)                       // 135168 : 64 x 528 = 33792
#define OFF_A1   (OFF_A0 + 64 * ROWB)               // 168960
#define OFF_WT   (OFF_A1 + 64 * ROWB)               // 202752 : 2 x 64 floats
#define OFF_B1   (OFF_WT + 512)                     // 256 floats
#define OFF_ITEM (OFF_B1 + 1024)
#define SM_TOTAL (OFF_ITEM + 16)                    // ~204.3 KB -> 1 block/SM

__global__ void __launch_bounds__(256, 1)
expert_kernel(const float* __restrict__ b1) {
    extern __shared__ char sm[];
    uint32_t smemu = smem_u32(sm);
    int tid = threadIdx.x;
    int warp = tid >> 5, lane = tid & 31;

    uint32_t aA_off = (uint32_t)((lane & 15) * ROWB + ((lane & 16) ? 16 : 0));
    uint32_t aB_off = (uint32_t)((warp * 32 + (lane & 7) + ((lane & 16) ? 8 : 0)) * ROWB
                                 + ((lane & 8) ? 16 : 0));
    int grow = tid >> 2, gseg = tid & 3;            // A gather: 64 rows x 4 x 128B
    int prevk = -1;

    for (;;) {
        if (tid == 0) *(int*)(sm + OFF_ITEM) = atomicAdd(&g_item, 1);
        __syncthreads();
        int item = *(int*)(sm + OFF_ITEM);
        if (item >= NITEMS) break;

        int k = item >> 5, b = (item >> 1) & 15, halfM = item & 1;   // k-major
        int bk = b * KK + k;
        int cnt = g_cnt[bk];
        int hc = (cnt + 1) >> 1;
        int start = halfM ? hc : 0;
        int myn = (halfM ? cnt : hc) - start;
        int ntiles = (myn + 63) >> 6;

        // ---- stage B = W1[k] via cp.async, only when k changes ----
        if (k != prevk) {
            const char* src = g_w1pad + ((size_t)(k * 256 + tid)) * ROWB;
            uint32_t dst = smemu + OFF_B + (uint32_t)tid * ROWB;
#pragma unroll 11
            for (int j = 0; j < 33; j++) CP_ASYNC16(dst + j * 16, src + j * 16);
            ((float*)(sm + OFF_B1))[tid] = b1[k * CC + tid];
            prevk = k;
        }
        // ---- prologue: A tile 0 + wt0 ----
        if (ntiles > 0) {
            int slot = start + grow;
            int n = (int)g_list[bk][slot < cnt ? slot : (cnt > 0 ? cnt - 1 : 0)];
            const char* src = (const char*)(g_tokbf + ((size_t)b * NN + n) * CC) + gseg * 128;
            uint32_t dst = smemu + OFF_A0 + grow * ROWB + gseg * 128;
#pragma unroll
            for (int j = 0; j < 8; j++) CP_ASYNC16(dst + j * 16, src + j * 16);
            if (tid < 64) {
                int s0 = start + tid;
                ((float*)(sm + OFF_WT))[tid] = (s0 < start + myn) ? g_wt[bk][s0] : 0.f;
            }
        }
        CP_COMMIT();
        CP_WAIT0();
        __syncthreads();

        float acc[4][4][4];                // [mtile16][n8][quad]
#pragma unroll
        for (int mt = 0; mt < 4; mt++)
#pragma unroll
            for (int n = 0; n < 4; n++)
#pragma unroll
                for (int q = 0; q < 4; q++) acc[mt][n][q] = 0.f;
        float colsum[4][2];
#pragma unroll
        for (int n = 0; n < 4; n++) colsum[n][0] = colsum[n][1] = 0.f;

        const float* sb1 = (const float*)(sm + OFF_B1);
        uint32_t aB_base = smemu + OFF_B + aB_off;

        for (int t = 0; t < ntiles; t++) {
            int cur = t & 1;
            uint32_t aA_base = smemu + (cur ? OFF_A1 : OFF_A0) + aA_off;

            // ---- prefetch next A tile into other buffer (covered by K-loop) ----
            if (t + 1 < ntiles) {
                int slot = start + (t + 1) * 64 + grow;
                int n = (int)g_list[bk][slot < cnt ? slot : cnt - 1];
                const char* src = (const char*)(g_tokbf + ((size_t)b * NN + n) * CC) + gseg * 128;
                uint32_t dst = smemu + (cur ? OFF_A0 : OFF_A1) + grow * ROWB + gseg * 128;
#pragma unroll
                for (int j = 0; j < 8; j++) CP_ASYNC16(dst + j * 16, src + j * 16);
                CP_COMMIT();
                if (tid < 64) {
                    int s2 = start + (t + 1) * 64 + tid;
                    ((float*)(sm + OFF_WT))[(1 - cur) * 64 + tid] =
                        (s2 < start + myn) ? g_wt[bk][s2] : 0.f;
                }
            }

            // ---- K loop: 16 steps, frag double-buffered: 6 LDSM -> 16 HMMA ----
            uint32_t fa[2][4][4], fb[2][8];
            LDSM4(fa[0][0], aA_base);
            LDSM4(fa[0][1], aA_base + 16 * ROWB);
            LDSM4(fa[0][2], aA_base + 32 * ROWB);
            LDSM4(fa[0][3], aA_base + 48 * ROWB);
            LDSM4(fb[0] + 0, aB_base);
            LDSM4(fb[0] + 4, aB_base + 16 * ROWB);
#pragma unroll
            for (int ks = 0; ks < 16; ks++) {
                int c = ks & 1, nx = 1 - c;
                if (ks < 15) {
                    uint32_t kb = (uint32_t)((ks + 1) * 32);
                    LDSM4(fa[nx][0], aA_base + kb);
                    LDSM4(fa[nx][1], aA_base + 16 * ROWB + kb);
                    LDSM4(fa[nx][2], aA_base + 32 * ROWB + kb);
                    LDSM4(fa[nx][3], aA_base + 48 * ROWB + kb);
                    LDSM4(fb[nx] + 0, aB_base + kb);
                    LDSM4(fb[nx] + 4, aB_base + 16 * ROWB + kb);
                }
#pragma unroll
                for (int mt = 0; mt < 4; mt++) {
                    mma16816(acc[mt][0], fa[c][mt], fb[c] + 0);
                    mma16816(acc[mt][1], fa[c][mt], fb[c] + 2);
                    mma16816(acc[mt][2], fa[c][mt], fb[c] + 4);
                    mma16816(acc[mt][3], fa[c][mt], fb[c] + 6);
                }
            }

            // ---- fused epilogue: colsum += w * relu(acc + b1) ----
            {
                const float* swt = (const float*)(sm + OFF_WT) + cur * 64;
#pragma unroll
                for (int mt = 0; mt < 4; mt++) {
                    int r0 = mt * 16 + (lane >> 2);
                    float w0 = swt[r0], w1 = swt[r0 + 8];
#pragma unroll
                    for (int n = 0; n < 4; n++) {
                        int c0 = warp * 32 + n * 8 + (lane & 3) * 2;
                        float bb0 = sb1[c0], bb1 = sb1[c0 + 1];
                        colsum[n][0] += w0 * fmaxf(acc[mt][n][0] + bb0, 0.f)
                                      + w1 * fmaxf(acc[mt][n][2] + bb0, 0.f);
                        colsum[n][1] += w0 * fmaxf(acc[mt][n][1] + bb1, 0.f)
                                      + w1 * fmaxf(acc[mt][n][3] + bb1, 0.f);
#pragma unroll
                        for (int q = 0; q < 4; q++) acc[mt][n][q] = 0.f;
                    }
                }
            }

            CP_WAIT0();
            __syncthreads();
        }

        // ---- reduce over 8 row-groups (shfl), atomic-accumulate into g_hacc ----
        if (ntiles > 0) {
#pragma unroll
            for (int n = 0; n < 4; n++)
#pragma unroll
                for (int q = 0; q < 2; q++) {
#pragma unroll
                    for (int off = 4; off <= 16; off <<= 1)
                        colsum[n][q] += __shfl_xor_sync(0xffffffffu, colsum[n][q], off);
                }
            if (lane < 4) {
#pragma unroll
                for (int n = 0; n < 4; n++) {
                    int c = warp * 32 + n * 8 + lane * 2;
                    atomicAdd(&g_hacc[bk * CC + c],     colsum[n][0]);
                    atomicAdd(&g_hacc[bk * CC + c + 1], colsum[n][1]);
                }
            }
        }
    }
}

// ------- layer-2 + normalize (blocks 0-511: (bk, c-quarter), split-K=4) + scalars (block 512) -------
__global__ void out_fin_kernel(const float* __restrict__ W2,
                               const float* __restrict__ b2,
                               float* __restrict__ out) {
    int tid = threadIdx.x;
    if (blockIdx.x == 512) {
        __shared__ float sred[256];
        float s = 0.f;
        for (int i = tid; i < GATE_BLOCKS; i += 256) s += g_conf[i];
        sred[tid] = s;
        __syncthreads();
        for (int off = 128; off; off >>= 1) {
            if (tid < off) sred[tid] += sred[tid + off];
            __syncthreads();
        }
        if (tid == 0) {
            float rc = sred[0] / (float)NTOK;
            float u[KK]; float mean = 0.f;
#pragma unroll
            for (int k = 0; k < KK; k++) {
                int c = 0;
#pragma unroll
                for (int b = 0; b < BB; b++) c += g_cnt[b * KK + k];
                u[k] = (float)c / (float)NTOK;
                mean += u[k];
            }
            mean /= (float)KK;
            float var = 0.f;
#pragma unroll
            for (int k = 0; k < KK; k++) { float d = u[k] - mean; var += d * d; }
            var /= (float)KK;
            float den = mean + EPSF;
            out[BB * KK * CC]     = var / (den * den);
            out[BB * KK * CC + 1] = rc;
        }
        return;
    }
    __shared__ float sh[CC];
    __shared__ float spar[256];
    int bk = blockIdx.x >> 2;
    int cq = blockIdx.x & 3;
    int k = bk & 7;
    int cl = tid & 63, kh = tid >> 6;        // 64 cols x split-K 4
    int c = cq * 64 + cl;
    sh[tid] = g_hacc[bk * CC + tid];
    __syncthreads();
    const float4* w4 = (const float4*)(W2 + ((size_t)k * CC + c) * CC + kh * 64);
    const float* shh = sh + kh * 64;
    float p0 = 0.f, p1 = 0.f, p2 = 0.f, p3 = 0.f;
#pragma unroll
    for (int j = 0; j < 16; j++) {
        float4 w = w4[j];
        p0 += shh[4*j]   * w.x;
        p1 += shh[4*j+1] * w.y;
        p2 += shh[4*j+2] * w.z;
        p3 += shh[4*j+3] * w.w;
    }
    spar[tid] = (p0 + p1) + (p2 + p3);
    __syncthreads();
    if (kh == 0) {
        float s = spar[cl] + spar[64 + cl] + spar[128 + cl] + spar[192 + cl];
        float mass = g_mass[bk];
        s += mass * b2[k * CC + c];
        s /= fmaxf(mass, EPSF);
        out[bk * CC + c] = s;
    }
}

// ---------------- launch ----------------
extern "C" void kernel_launch(void* const* d_in, const int* in_sizes, int n_in,
                              void* d_out, int out_size) {
    const float* tokens = (const float*)d_in[0];
    const float* geno   = (const float*)d_in[1];
    const float* Wg     = (const float*)d_in[2];
    const float* bg     = (const float*)d_in[3];
    const float* Wgg    = (const float*)d_in[4];
    const float* bgg    = (const float*)d_in[5];
    const float* W1     = (const float*)d_in[6];
    const float* b1     = (const float*)d_in[7];
    const float* W2     = (const float*)d_in[8];
    const float* b2     = (const float*)d_in[9];
    float* out = (float*)d_out;

    cudaFuncSetAttribute(expert_kernel, cudaFuncAttributeMaxDynamicSharedMemorySize, SM_TOTAL);

    gate_kernel<<<GATE_BLOCKS + 128, 256>>>(tokens, Wg, bg, geno, Wgg, bgg, W1);
    compact_kernel<<<129, 256>>>();
    expert_kernel<<<148, 256, SM_TOTAL>>>(b1);
    out_fin_kernel<<<513, 256>>>(W2, b2, out);
}

// round 16
// speedup vs baseline: 1.0341x; 1.0341x over previous
#include <cuda_runtime.h>
#include <cuda_bf16.h>
#include <math.h>
#include <stdint.h>

#define BB 16
#define NN 4096
#define CC 256
#define KK 8
#define EPSF 1e-6f
#define RATIOF 0.1f
#define NTOK (BB*NN)          // 65536
#define GATE_BLOCKS (NTOK/16) // 4096
#define NITEMS (BB*KK*2)      // 256 expert items: (b,k,halfM)
#define ROWB 528

// ---------------- scratch globals ----------------
__device__ unsigned short g_route_e[NTOK];
__device__ float2         g_route_w[NTOK];
__device__ float          g_conf[GATE_BLOCKS];
__device__ float          g_hacc[BB*KK*CC];
__device__ float          g_mass[BB*KK];
__device__ unsigned short g_list[BB*KK][NN];
__device__ float          g_wt[BB*KK][NN];
__device__ int            g_cnt[BB*KK];
__device__ int            g_item;
__device__ __nv_bfloat16  g_tokbf[(size_t)NTOK*CC];       // bf16 tokens (gate writes)
__device__ char           g_w1pad[(size_t)KK*256*ROWB];   // W1 bf16, padded rows

// ---------------- helpers ----------------
__device__ __forceinline__ uint32_t smem_u32(const void* p) {
    uint32_t a;
    asm("{ .reg .u64 t; cvta.to.shared.u64 t, %1; cvt.u32.u64 %0, t; }" : "=r"(a) : "l"(p));
    return a;
}
__device__ __forceinline__ uint32_t pack_bf2(float a, float b) {
    uint32_t r;
    asm("cvt.rn.bf16x2.f32 %0, %1, %2;" : "=r"(r) : "f"(b), "f"(a));
    return r;
}
__device__ __forceinline__ void mma16816(float* c, const uint32_t* a, const uint32_t* b) {
    asm volatile("mma.sync.aligned.m16n8k16.row.col.f32.bf16.bf16.f32 "
        "{%0,%1,%2,%3}, {%4,%5,%6,%7}, {%8,%9}, {%0,%1,%2,%3};"
        : "+f"(c[0]), "+f"(c[1]), "+f"(c[2]), "+f"(c[3])
        : "r"(a[0]), "r"(a[1]), "r"(a[2]), "r"(a[3]), "r"(b[0]), "r"(b[1]));
}
#define LDSM4(r, addr) \
    asm volatile("ldmatrix.sync.aligned.m8n8.x4.shared.b16 {%0,%1,%2,%3}, [%4];" \
        : "=r"((r)[0]), "=r"((r)[1]), "=r"((r)[2]), "=r"((r)[3]) : "r"(addr))
#define CP_ASYNC16(dst, src) \
    asm volatile("cp.async.cg.shared.global [%0], [%1], 16;" :: "r"(dst), "l"(src))
#define CP_COMMIT() asm volatile("cp.async.commit_group;" ::: "memory")
#define CP_WAIT0()  asm volatile("cp.async.wait_group 0;" ::: "memory")

// ---------------- gate: geno (in-block) + logits/top-2/softmax + bf16 copy ----------------
__global__ void gate_kernel(const float* __restrict__ tokens,
                            const float* __restrict__ Wg,
                            const float* __restrict__ bg,
                            const float* __restrict__ geno_vec,
                            const float* __restrict__ Wgg,
                            const float* __restrict__ bgg) {
    __shared__ float4 sWg[KK * 64];
    __shared__ float  sconf[16];
    __shared__ float  sbg[8], sgeno[8];
    int tid = threadIdx.x;
    int warp = tid >> 5, lane = tid & 31;
    int b = (blockIdx.x * 16) >> 12;

    for (int i = tid; i < KK * 64; i += 256) sWg[i] = ((const float4*)Wg)[i];
    // per-block geno term: warp w computes k=w
    {
        const float4* g4 = (const float4*)(geno_vec + b * CC);
        const float4* w4 = (const float4*)(Wgg + warp * CC);
        float4 ga = g4[lane * 2], gb = g4[lane * 2 + 1];
        float4 wa = w4[lane * 2], wb = w4[lane * 2 + 1];
        float d = ga.x * wa.x + ga.y * wa.y + ga.z * wa.z + ga.w * wa.w
                + gb.x * wb.x + gb.y * wb.y + gb.z * wb.z + gb.w * wb.w;
#pragma unroll
        for (int off = 16; off; off >>= 1) d += __shfl_xor_sync(0xffffffffu, d, off);
        if (lane == 0) sgeno[warp] = RATIOF * (d + bgg[warp]);
    }
    if (tid < 8) sbg[tid] = bg[tid];
    __syncthreads();

    int t0 = blockIdx.x * 16 + warp * 2;

    float acc[2][KK];
#pragma unroll
    for (int u = 0; u < 2; u++)
#pragma unroll
        for (int k = 0; k < KK; k++) acc[u][k] = 0.f;

    uint2* bf0 = (uint2*)(g_tokbf + (size_t)t0 * CC);
    uint2* bf1 = (uint2*)(g_tokbf + (size_t)(t0 + 1) * CC);
#pragma unroll
    for (int i = 0; i < 2; i++) {
        float4 tv0 = ((const float4*)(tokens + (size_t)t0 * CC))[i * 32 + lane];
        float4 tv1 = ((const float4*)(tokens + (size_t)(t0 + 1) * CC))[i * 32 + lane];
        bf0[i * 32 + lane] = make_uint2(pack_bf2(tv0.x, tv0.y), pack_bf2(tv0.z, tv0.w));
        bf1[i * 32 + lane] = make_uint2(pack_bf2(tv1.x, tv1.y), pack_bf2(tv1.z, tv1.w));
#pragma unroll
        for (int k = 0; k < KK; k++) {
            float4 w = sWg[k * 64 + i * 32 + lane];
            acc[0][k] += tv0.x * w.x + tv0.y * w.y + tv0.z * w.z + tv0.w * w.w;
            acc[1][k] += tv1.x * w.x + tv1.y * w.y + tv1.z * w.z + tv1.w * w.w;
        }
    }

    // multi-field butterfly reduce: 16 (token,k) fields over 32 lanes
    const unsigned FM = 0xffffffffu;
    float tt[8];
#pragma unroll
    for (int kk = 0; kk < 8; kk++) {
        float send = (lane & 16) ? acc[0][kk] : acc[1][kk];
        float keep = (lane & 16) ? acc[1][kk] : acc[0][kk];
        tt[kk] = keep + __shfl_xor_sync(FM, send, 16);
    }
    float uu[4];
#pragma unroll
    for (int j = 0; j < 4; j++) {
        float send = (lane & 8) ? tt[j] : tt[j + 4];
        float keep = (lane & 8) ? tt[j + 4] : tt[j];
        uu[j] = keep + __shfl_xor_sync(FM, send, 8);
    }
    float vv[2];
#pragma unroll
    for (int j = 0; j < 2; j++) {
        float send = (lane & 4) ? uu[j] : uu[j + 2];
        float keep = (lane & 4) ? uu[j + 2] : uu[j];
        vv[j] = keep + __shfl_xor_sync(FM, send, 4);
    }
    float ww;
    {
        float send = (lane & 2) ? vv[0] : vv[1];
        float keep = (lane & 2) ? vv[1] : vv[0];
        ww = keep + __shfl_xor_sync(FM, send, 2);
    }
    ww += __shfl_xor_sync(FM, ww, 1);

    float gk[8];
#pragma unroll
    for (int k = 0; k < 8; k++)
        gk[k] = __shfl_sync(FM, ww, (lane & 16) | (k << 1));

    if ((lane & 15) == 0) {
        int u = lane >> 4;
        int t = t0 + u;
        float lg[KK];
#pragma unroll
        for (int k = 0; k < KK; k++) lg[k] = gk[k] + sbg[k] + sgeno[k];
        int i0 = 0; float v0 = lg[0];
#pragma unroll
        for (int k = 1; k < KK; k++) if (lg[k] > v0) { v0 = lg[k]; i0 = k; }
        float v1 = -1e30f; int i1 = 0;
#pragma unroll
        for (int k = 0; k < KK; k++)
            if (k != i0 && lg[k] > v1) { v1 = lg[k]; i1 = k; }
        float e  = expf(v1 - v0);
        float w0 = 1.f / (1.f + e);
        float w1 = e / (1.f + e);
        w0 = fmaxf(w0, EPSF); w1 = fmaxf(w1, EPSF);
        float s = w0 + w1; w0 /= s; w1 /= s;
        g_route_e[t] = (unsigned short)(i0 | (i1 << 8));
        g_route_w[t] = make_float2(w0, w1);
        sconf[warp * 2 + u] = v0 - v1;
    }
    __syncthreads();
    if (tid == 0) {
        float cs = 0.f;
#pragma unroll
        for (int w = 0; w < 16; w++) cs += sconf[w];
        g_conf[blockIdx.x] = cs;
    }
}

// ------- compaction (0-127) + w1pad (128-255) + hacc zero/counter (256) -------
__global__ void compact_w1_kernel(const float* __restrict__ W1) {
    int tid = threadIdx.x;
    if (blockIdx.x == 256) {
        float4* h4 = (float4*)g_hacc;
        for (int i = tid; i < BB * KK * CC / 4; i += 256)
            h4[i] = make_float4(0.f, 0.f, 0.f, 0.f);
        if (tid == 0) g_item = 0;
        return;
    }
    if (blockIdx.x >= 128) {
        int gid = (blockIdx.x - 128) * 256 + tid;
        int row = gid >> 4, seg = gid & 15;
        const float4* src = (const float4*)(W1 + (size_t)row * CC) + seg * 4;
        char* dst = g_w1pad + (size_t)row * ROWB + seg * 32;
#pragma unroll
        for (int j = 0; j < 4; j++) {
            float4 v = src[j];
            *(uint2*)(dst + j * 8) = make_uint2(pack_bf2(v.x, v.y), pack_bf2(v.z, v.w));
        }
        return;
    }
    __shared__ int   scnt[8];
    __shared__ float smass[8];
    __shared__ int   soff[8];
    int bk = blockIdx.x;
    int b = bk >> 3, k = bk & 7;
    int warp = tid >> 5, lane = tid & 31;

    int cnt = 0; float mass = 0.f;
    int base0 = warp * 512;
    for (int i = 0; i < 16; i++) {
        int n = base0 + i * 32 + lane;
        unsigned short e = g_route_e[b * NN + n];
        float2 wv = g_route_w[b * NN + n];
        bool m0 = (e & 0xff) == k;
        bool m1 = (e >> 8)   == k;
        bool hit = m0 || m1;
        unsigned bal = __ballot_sync(0xffffffffu, hit);
        cnt += __popc(bal);
        if (hit) mass += m0 ? wv.x : wv.y;
    }
#pragma unroll
    for (int off = 16; off; off >>= 1) mass += __shfl_xor_sync(0xffffffffu, mass, off);
    if (lane == 0) { scnt[warp] = cnt; smass[warp] = mass; }
    __syncthreads();
    if (tid == 0) {
        int run = 0; float msum = 0.f;
#pragma unroll
        for (int w = 0; w < 8; w++) { soff[w] = run; run += scnt[w]; msum += smass[w]; }
        g_cnt[bk] = run;
        g_mass[bk] = msum;
    }
    __syncthreads();

    int pos = soff[warp];
    for (int i = 0; i < 16; i++) {
        int n = base0 + i * 32 + lane;
        unsigned short e = g_route_e[b * NN + n];
        float2 wv = g_route_w[b * NN + n];
        bool m0 = (e & 0xff) == k;
        bool m1 = (e >> 8)   == k;
        bool hit = m0 || m1;
        unsigned bal = __ballot_sync(0xffffffffu, hit);
        if (hit) {
            int p = pos + __popc(bal & ((1u << lane) - 1u));
            g_list[bk][p] = (unsigned short)n;
            g_wt[bk][p]   = m0 ? wv.x : wv.y;
        }
        pos += __popc(bal);
    }
}

// ================= expert: 1 block/SM, M=64 x N=256, 8 warps of 64x32, A dbl-buf =================
#define OFF_B    0                                  // 256 x 528 = 135168
#define OFF_A0   (256 * ROWB)                       // 135168 : 64 x 528 = 33792
#define OFF_A1   (OFF_A0 + 64 * ROWB)               // 168960
#define OFF_WT   (OFF_A1 + 64 * ROWB)               // 202752 : 2 x 64 floats
#define OFF_B1   (OFF_WT + 512)                     // 256 floats
#define OFF_ITEM (OFF_B1 + 1024)
#define SM_TOTAL (OFF_ITEM + 16)                    // ~204.3 KB -> 1 block/SM

__global__ void __launch_bounds__(256, 1)
expert_kernel(const float* __restrict__ b1) {
    extern __shared__ char sm[];
    uint32_t smemu = smem_u32(sm);
    int tid = threadIdx.x;
    int warp = tid >> 5, lane = tid & 31;

    uint32_t aA_off = (uint32_t)((lane & 15) * ROWB + ((lane & 16) ? 16 : 0));
    uint32_t aB_off = (uint32_t)((warp * 32 + (lane & 7) + ((lane & 16) ? 8 : 0)) * ROWB
                                 + ((lane & 8) ? 16 : 0));
    int grow = tid >> 2, gseg = tid & 3;            // A gather: 64 rows x 4 x 128B

    for (;;) {
        if (tid == 0) *(int*)(sm + OFF_ITEM) = atomicAdd(&g_item, 1);
        __syncthreads();
        int item = *(int*)(sm + OFF_ITEM);
        if (item >= NITEMS) break;

        int b = item >> 4, k = (item >> 1) & 7, halfM = item & 1;
        int bk = b * KK + k;
        int cnt = g_cnt[bk];
        int hc = (cnt + 1) >> 1;
        int start = halfM ? hc : 0;
        int myn = (halfM ? cnt : hc) - start;
        int ntiles = (myn + 63) >> 6;

        // ---- stage full B = W1[k] (256 rows) via cp.async ----
        {
            const char* src = g_w1pad + ((size_t)(k * 256 + tid)) * ROWB;
            uint32_t dst = smemu + OFF_B + (uint32_t)tid * ROWB;
#pragma unroll 11
            for (int j = 0; j < 33; j++) CP_ASYNC16(dst + j * 16, src + j * 16);
        }
        // ---- prologue: A tile 0 + wt0 ----
        if (ntiles > 0) {
            int slot = start + grow;
            int n = (int)g_list[bk][slot < cnt ? slot : (cnt > 0 ? cnt - 1 : 0)];
            const char* src = (const char*)(g_tokbf + ((size_t)b * NN + n) * CC) + gseg * 128;
            uint32_t dst = smemu + OFF_A0 + grow * ROWB + gseg * 128;
#pragma unroll
            for (int j = 0; j < 8; j++) CP_ASYNC16(dst + j * 16, src + j * 16);
            if (tid < 64) {
                int s0 = start + tid;
                ((float*)(sm + OFF_WT))[tid] = (s0 < start + myn) ? g_wt[bk][s0] : 0.f;
            }
        }
        ((float*)(sm + OFF_B1))[tid] = b1[k * CC + tid];
        CP_COMMIT();
        CP_WAIT0();
        __syncthreads();

        float acc[4][4][4];                // [mtile16][n8][quad]
#pragma unroll
        for (int mt = 0; mt < 4; mt++)
#pragma unroll
            for (int n = 0; n < 4; n++)
#pragma unroll
                for (int q = 0; q < 4; q++) acc[mt][n][q] = 0.f;
        float colsum[4][2];
#pragma unroll
        for (int n = 0; n < 4; n++) colsum[n][0] = colsum[n][1] = 0.f;

        const float* sb1 = (const float*)(sm + OFF_B1);
        uint32_t aB_base = smemu + OFF_B + aB_off;

        for (int t = 0; t < ntiles; t++) {
            int cur = t & 1;
            uint32_t aA_base = smemu + (cur ? OFF_A1 : OFF_A0) + aA_off;

            // ---- prefetch next A tile into other buffer (covered by K-loop) ----
            if (t + 1 < ntiles) {
                int slot = start + (t + 1) * 64 + grow;
                int n = (int)g_list[bk][slot < cnt ? slot : cnt - 1];
                const char* src = (const char*)(g_tokbf + ((size_t)b * NN + n) * CC) + gseg * 128;
                uint32_t dst = smemu + (cur ? OFF_A0 : OFF_A1) + grow * ROWB + gseg * 128;
#pragma unroll
                for (int j = 0; j < 8; j++) CP_ASYNC16(dst + j * 16, src + j * 16);
                CP_COMMIT();
                if (tid < 64) {
                    int s2 = start + (t + 1) * 64 + tid;
                    ((float*)(sm + OFF_WT))[(1 - cur) * 64 + tid] =
                        (s2 < start + myn) ? g_wt[bk][s2] : 0.f;
                }
            }

            // ---- K loop: 16 steps, frag double-buffered: 6 LDSM -> 16 HMMA ----
            uint32_t fa[2][4][4], fb[2][8];
            LDSM4(fa[0][0], aA_base);
            LDSM4(fa[0][1], aA_base + 16 * ROWB);
            LDSM4(fa[0][2], aA_base + 32 * ROWB);
            LDSM4(fa[0][3], aA_base + 48 * ROWB);
            LDSM4(fb[0] + 0, aB_base);
            LDSM4(fb[0] + 4, aB_base + 16 * ROWB);
#pragma unroll
            for (int ks = 0; ks < 16; ks++) {
                int c = ks & 1, nx = 1 - c;
                if (ks < 15) {
                    uint32_t kb = (uint32_t)((ks + 1) * 32);
                    LDSM4(fa[nx][0], aA_base + kb);
                    LDSM4(fa[nx][1], aA_base + 16 * ROWB + kb);
                    LDSM4(fa[nx][2], aA_base + 32 * ROWB + kb);
                    LDSM4(fa[nx][3], aA_base + 48 * ROWB + kb);
                    LDSM4(fb[nx] + 0, aB_base + kb);
                    LDSM4(fb[nx] + 4, aB_base + 16 * ROWB + kb);
                }
#pragma unroll
                for (int mt = 0; mt < 4; mt++) {
                    mma16816(acc[mt][0], fa[c][mt], fb[c] + 0);
                    mma16816(acc[mt][1], fa[c][mt], fb[c] + 2);
                    mma16816(acc[mt][2], fa[c][mt], fb[c] + 4);
                    mma16816(acc[mt][3], fa[c][mt], fb[c] + 6);
                }
            }

            // ---- fused epilogue: colsum += w * relu(acc + b1) ----
            {
                const float* swt = (const float*)(sm + OFF_WT) + cur * 64;
#pragma unroll
                for (int mt = 0; mt < 4; mt++) {
                    int r0 = mt * 16 + (lane >> 2);
                    float w0 = swt[r0], w1 = swt[r0 + 8];
#pragma unroll
                    for (int n = 0; n < 4; n++) {
                        int c0 = warp * 32 + n * 8 + (lane & 3) * 2;
                        float bb0 = sb1[c0], bb1 = sb1[c0 + 1];
                        colsum[n][0] += w0 * fmaxf(acc[mt][n][0] + bb0, 0.f)
                                      + w1 * fmaxf(acc[mt][n][2] + bb0, 0.f);
                        colsum[n][1] += w0 * fmaxf(acc[mt][n][1] + bb1, 0.f)
                                      + w1 * fmaxf(acc[mt][n][3] + bb1, 0.f);
#pragma unroll
                        for (int q = 0; q < 4; q++) acc[mt][n][q] = 0.f;
                    }
                }
            }

            CP_WAIT0();
            __syncthreads();
        }

        // ---- reduce over 8 row-groups (shfl), atomic-accumulate into g_hacc ----
        if (ntiles > 0) {
#pragma unroll
            for (int n = 0; n < 4; n++)
#pragma unroll
                for (int q = 0; q < 2; q++) {
#pragma unroll
                    for (int off = 4; off <= 16; off <<= 1)
                        colsum[n][q] += __shfl_xor_sync(0xffffffffu, colsum[n][q], off);
                }
            if (lane < 4) {
#pragma unroll
                for (int n = 0; n < 4; n++) {
                    int c = warp * 32 + n * 8 + lane * 2;
                    atomicAdd(&g_hacc[bk * CC + c],     colsum[n][0]);
                    atomicAdd(&g_hacc[bk * CC + c + 1], colsum[n][1]);
                }
            }
        }
    }
}

// ------- layer-2 (blocks 0-127, warp-per-row coalesced) + scalars (block 128) -------
__global__ void out_fin_kernel(const float* __restrict__ W2,
                               const float* __restrict__ b2,
                               float* __restrict__ out) {
    int tid = threadIdx.x;
    if (blockIdx.x == 128) {
        __shared__ float sred[512];
        float s = 0.f;
        for (int i = tid; i < GATE_BLOCKS; i += 512) s += g_conf[i];
        sred[tid] = s;
        __syncthreads();
        for (int off = 256; off; off >>= 1) {
            if (tid < off) sred[tid] += sred[tid + off];
            __syncthreads();
        }
        if (tid == 0) {
            float rc = sred[0] / (float)NTOK;
            float u[KK]; float mean = 0.f;
#pragma unroll
            for (int k = 0; k < KK; k++) {
                int c = 0;
#pragma unroll
                for (int b = 0; b < BB; b++) c += g_cnt[b * KK + k];
                u[k] = (float)c / (float)NTOK;
                mean += u[k];
            }
            mean /= (float)KK;
            float var = 0.f;
#pragma unroll
            for (int k = 0; k < KK; k++) { float d = u[k] - mean; var += d * d; }
            var /= (float)KK;
            float den = mean + EPSF;
            out[BB * KK * CC]     = var / (den * den);
            out[BB * KK * CC + 1] = rc;
        }
        return;
    }
    // blocks 0-127: one bk per block, 512 threads = 16 warps, warp-per-row (16 rows each)
    __shared__ float sh[CC];
    int bk = blockIdx.x;
    int k = bk & 7;
    int warp = tid >> 5, lane = tid & 31;
    if (tid < CC) sh[tid] = g_hacc[bk * CC + tid];
    __syncthreads();
    float mass = g_mass[bk];
    float den = fmaxf(mass, EPSF);
    const float4* w2k = (const float4*)(W2 + (size_t)k * CC * CC);
    const float* shl = sh + lane * 8;
#pragma unroll 4
    for (int i = 0; i < 16; i++) {
        int c = warp * 16 + i;
        // coalesced: lane reads floats [lane*8, lane*8+8) of row c
        float4 wa = w2k[c * 64 + lane * 2];
        float4 wb = w2k[c * 64 + lane * 2 + 1];
        float d = wa.x * shl[0] + wa.y * shl[1] + wa.z * shl[2] + wa.w * shl[3]
                + wb.x * shl[4] + wb.y * shl[5] + wb.z * shl[6] + wb.w * shl[7];
#pragma unroll
        for (int off = 16; off; off >>= 1)
            d += __shfl_xor_sync(0xffffffffu, d, off);
        if (lane == 0)
            out[bk * CC + c] = (d + mass * b2[k * CC + c]) / den;
    }
}

// ---------------- launch ----------------
extern "C" void kernel_launch(void* const* d_in, const int* in_sizes, int n_in,
                              void* d_out, int out_size) {
    const float* tokens = (const float*)d_in[0];
    const float* geno   = (const float*)d_in[1];
    const float* Wg     = (const float*)d_in[2];
    const float* bg     = (const float*)d_in[3];
    const float* Wgg    = (const float*)d_in[4];
    const float* bgg    = (const float*)d_in[5];
    const float* W1     = (const float*)d_in[6];
    const float* b1     = (const float*)d_in[7];
    const float* W2     = (const float*)d_in[8];
    const float* b2     = (const float*)d_in[9];
    float* out = (float*)d_out;

    cudaFuncSetAttribute(expert_kernel, cudaFuncAttributeMaxDynamicSharedMemorySize, SM_TOTAL);

    gate_kernel<<<GATE_BLOCKS, 256>>>(tokens, Wg, bg, geno, Wgg, bgg);
    compact_w1_kernel<<<257, 256>>>(W1);
    expert_kernel<<<148, 256, SM_TOTAL>>>(b1);
    out_fin_kernel<<<129, 512>>>(W2, b2, out);
}